// round 15
// baseline (speedup 1.0000x reference)
#include <cuda_runtime.h>
#include <cuda_bf16.h>
#include <cstdint>

#define D_MODEL 2048
#define D_KV    512
#define HQ      16
#define DH      128
#define BATCH   2
#define TSEQ    2048
#define MROWS   (BATCH * TSEQ)   // 4096

// ---------------- scratch (__device__ globals; no allocation allowed) -------
__device__ __nv_bfloat16 g_xh[MROWS * D_MODEL];
__device__ __nv_bfloat16 g_xl[MROWS * D_MODEL];
__device__ __nv_bfloat16 g_wqh[D_MODEL * D_MODEL];
__device__ __nv_bfloat16 g_wql[D_MODEL * D_MODEL];
__device__ __nv_bfloat16 g_wkh[D_MODEL * D_KV];
__device__ __nv_bfloat16 g_wkl[D_MODEL * D_KV];
__device__ __nv_bfloat16 g_wvh[D_MODEL * D_KV];
__device__ __nv_bfloat16 g_wvl[D_MODEL * D_KV];
__device__ __nv_bfloat16 g_woh[D_MODEL * D_MODEL];
__device__ __nv_bfloat16 g_wol[D_MODEL * D_MODEL];

__device__ __nv_bfloat16 g_qh[MROWS * D_MODEL];
__device__ __nv_bfloat16 g_ql[MROWS * D_MODEL];
__device__ __nv_bfloat16 g_kh[MROWS * D_KV];
__device__ __nv_bfloat16 g_kl[MROWS * D_KV];
__device__ __nv_bfloat16 g_vh[MROWS * D_KV];
__device__ __nv_bfloat16 g_vl[MROWS * D_KV];
__device__ __nv_bfloat16 g_ah[MROWS * D_MODEL];
__device__ __nv_bfloat16 g_al[MROWS * D_MODEL];

// ---------------------------------------------------------------------------
// merged fp32 -> (bf16 hi, lo) split, 8 floats/thread.
// ---------------------------------------------------------------------------
__global__ void __launch_bounds__(256) split_all(
    const float* __restrict__ x,  const float* __restrict__ Wq,
    const float* __restrict__ Wk, const float* __restrict__ Wv,
    const float* __restrict__ Wo,
    __nv_bfloat16* __restrict__ xh,  __nv_bfloat16* __restrict__ xl,
    __nv_bfloat16* __restrict__ wqh, __nv_bfloat16* __restrict__ wql,
    __nv_bfloat16* __restrict__ wkh, __nv_bfloat16* __restrict__ wkl,
    __nv_bfloat16* __restrict__ wvh, __nv_bfloat16* __restrict__ wvl,
    __nv_bfloat16* __restrict__ woh, __nv_bfloat16* __restrict__ wol)
{
    const int b = blockIdx.x;
    const float* s;
    __nv_bfloat16 *hi, *lo;
    int base;
    if (b < 4096)      { s = x;  hi = xh;  lo = xl;  base = b; }
    else if (b < 6144) { s = Wq; hi = wqh; lo = wql; base = b - 4096; }
    else if (b < 6656) { s = Wk; hi = wkh; lo = wkl; base = b - 6144; }
    else if (b < 7168) { s = Wv; hi = wvh; lo = wvl; base = b - 6656; }
    else               { s = Wo; hi = woh; lo = wol; base = b - 7168; }

    #pragma unroll
    for (int u = 0; u < 2; u++) {
        size_t i = (size_t)base * 2048 + u * 1024 + threadIdx.x * 4;
        float4 v = *(const float4*)(s + i);
        float f[4] = {v.x, v.y, v.z, v.w};
        __nv_bfloat16 h[4], l[4];
        #pragma unroll
        for (int j = 0; j < 4; j++) {
            h[j] = __float2bfloat16(f[j]);
            l[j] = __float2bfloat16(f[j] - __bfloat162float(h[j]));
        }
        ((__nv_bfloat162*)(hi + i))[0] = __nv_bfloat162(h[0], h[1]);
        ((__nv_bfloat162*)(hi + i))[1] = __nv_bfloat162(h[2], h[3]);
        ((__nv_bfloat162*)(lo + i))[0] = __nv_bfloat162(l[0], l[1]);
        ((__nv_bfloat162*)(lo + i))[1] = __nv_bfloat162(l[2], l[3]);
    }
}

// ---------------------------------------------------------------------------
// helpers
// ---------------------------------------------------------------------------
__device__ __forceinline__ uint32_t smem_u32(const void* p) {
    return (uint32_t)__cvta_generic_to_shared(p);
}
__device__ __forceinline__ void cp16(uint32_t d, const void* s) {
    asm volatile("cp.async.cg.shared.global [%0], [%1], 16;\n" :: "r"(d), "l"(s));
}
__device__ __forceinline__ void ldsm4(uint32_t* r, uint32_t a) {
    asm volatile("ldmatrix.sync.aligned.m8n8.x4.shared.b16 {%0,%1,%2,%3}, [%4];"
        : "=r"(r[0]), "=r"(r[1]), "=r"(r[2]), "=r"(r[3]) : "r"(a));
}
__device__ __forceinline__ void ldsm4t(uint32_t* r, uint32_t a) {
    asm volatile("ldmatrix.sync.aligned.m8n8.x4.trans.shared.b16 {%0,%1,%2,%3}, [%4];"
        : "=r"(r[0]), "=r"(r[1]), "=r"(r[2]), "=r"(r[3]) : "r"(a));
}
__device__ __forceinline__ void mma16816(float* d, const uint32_t* a,
                                         uint32_t b0, uint32_t b1) {
    asm volatile(
        "mma.sync.aligned.m16n8k16.row.col.f32.bf16.bf16.f32 "
        "{%0,%1,%2,%3}, {%4,%5,%6,%7}, {%8,%9}, {%0,%1,%2,%3};"
        : "+f"(d[0]), "+f"(d[1]), "+f"(d[2]), "+f"(d[3])
        : "r"(a[0]), "r"(a[1]), "r"(a[2]), "r"(a[3]), "r"(b0), "r"(b1));
}
__device__ __forceinline__ uint32_t pack_bf2(float x, float y) {
    __nv_bfloat162 t(__float2bfloat16(x), __float2bfloat16(y));
    return *(uint32_t*)&t;
}

// ---------------------------------------------------------------------------
// GEMM core: 2-term bf16 split, 128x128x32 tile, 3-stage cp.async pipeline,
// 2 CTAs/SM. Inner loop phase-ordered (hh -> hl -> lh) to cut peak fragment
// liveness from 64 to 48 regs. Lo-term regions: A at +A_TILE elements
// (= A_TILE*2 bytes), B at +B_TILE elements, matching load_stage layout.
// ---------------------------------------------------------------------------
#define BM 128
#define BN 128
#define BK 32
#define AST 40
#define BST 136
#define A_TILE (BM * AST)
#define B_TILE (BK * BST)
#define STAGE_ELEMS (2 * A_TILE + 2 * B_TILE)
#define GEMM_STAGES 3
#define GEMM_SMEM_BYTES (GEMM_STAGES * STAGE_ELEMS * 2)

template<int OUT_MODE>
__device__ __forceinline__ void gemm_core(
    const __nv_bfloat16* __restrict__ Ah, const __nv_bfloat16* __restrict__ Al,
    const __nv_bfloat16* __restrict__ Bh, const __nv_bfloat16* __restrict__ Bl,
    const float* __restrict__ bias, float* __restrict__ C,
    __nv_bfloat16* __restrict__ Ch, __nv_bfloat16* __restrict__ Cl,
    int N, int K, int am0, int bn0, __nv_bfloat16* sm)
{
    const int tid = threadIdx.x;
    const int lane = tid & 31;
    const int wid = tid >> 5;
    const int wr = wid >> 2;
    const int wc = wid & 3;

    float acc[4][4][4];
    #pragma unroll
    for (int mt = 0; mt < 4; mt++)
        #pragma unroll
        for (int nt = 0; nt < 4; nt++)
            #pragma unroll
            for (int e = 0; e < 4; e++) acc[mt][nt][e] = 0.f;

    auto load_stage = [&](int kt, int s) {
        const int k0 = kt * BK;
        __nv_bfloat16* base = sm + s * STAGE_ELEMS;
        #pragma unroll
        for (int i = 0; i < 2; i++) {
            int idx = tid + i * 256;
            int row = idx >> 2, ch = idx & 3;
            uint32_t d = smem_u32(base + row * AST + ch * 8);
            const size_t g = (size_t)(am0 + row) * K + k0 + ch * 8;
            cp16(d, Ah + g);
            cp16(d + A_TILE * 2, Al + g);       // +A_TILE*2 BYTES (u32 addr)
        }
        #pragma unroll
        for (int i = 0; i < 2; i++) {
            int idx = tid + i * 256;
            int row = idx >> 4, ch = idx & 15;
            uint32_t d = smem_u32(base + 2 * A_TILE + row * BST + ch * 8);
            const size_t g = (size_t)(k0 + row) * N + bn0 + ch * 8;
            cp16(d, Bh + g);
            cp16(d + B_TILE * 2, Bl + g);       // +B_TILE*2 BYTES (u32 addr)
        }
    };

    auto compute_stage = [&](int s) {
        __nv_bfloat16* base = sm + s * STAGE_ELEMS;
        const int sub = lane >> 3, r = lane & 7;
        #pragma unroll
        for (int ks = 0; ks < 2; ks++) {
            const int arow = wr * 64 + ((sub & 1) << 3) + r;
            const int acol = ks * 16 + ((sub >> 1) << 3);
            const int krow = ks * 16 + ((sub & 1) << 3) + r;
            const int ncol0 = wc * 32 + ((sub >> 1) << 3);

            // phase 1: ah + bh -> 16 hh MMAs
            uint32_t ah[4][4], bh[2][4];
            #pragma unroll
            for (int mt = 0; mt < 4; mt++)
                ldsm4(ah[mt], smem_u32(base + (arow + mt * 16) * AST + acol));
            #pragma unroll
            for (int ng = 0; ng < 2; ng++)
                ldsm4t(bh[ng], smem_u32(base + 2 * A_TILE + krow * BST +
                                        ncol0 + ng * 16));
            #pragma unroll
            for (int mt = 0; mt < 4; mt++)
                #pragma unroll
                for (int nt = 0; nt < 4; nt++) {
                    int ng = nt >> 1, o = (nt & 1) * 2;
                    mma16816(acc[mt][nt], ah[mt], bh[ng][o], bh[ng][o + 1]);
                }

            // phase 2: bl (ELEMENT offset B_TILE past bh) -> 16 hl MMAs
            uint32_t bl[2][4];
            #pragma unroll
            for (int ng = 0; ng < 2; ng++)
                ldsm4t(bl[ng], smem_u32(base + 2 * A_TILE + B_TILE +
                                        krow * BST + ncol0 + ng * 16));
            #pragma unroll
            for (int mt = 0; mt < 4; mt++)
                #pragma unroll
                for (int nt = 0; nt < 4; nt++) {
                    int ng = nt >> 1, o = (nt & 1) * 2;
                    mma16816(acc[mt][nt], ah[mt], bl[ng][o], bl[ng][o + 1]);
                }

            // phase 3: al (ELEMENT offset A_TILE past ah) -> 16 lh MMAs
            uint32_t al[4][4];
            #pragma unroll
            for (int mt = 0; mt < 4; mt++)
                ldsm4(al[mt], smem_u32(base + A_TILE +
                                       (arow + mt * 16) * AST + acol));
            #pragma unroll
            for (int mt = 0; mt < 4; mt++)
                #pragma unroll
                for (int nt = 0; nt < 4; nt++) {
                    int ng = nt >> 1, o = (nt & 1) * 2;
                    mma16816(acc[mt][nt], al[mt], bh[ng][o], bh[ng][o + 1]);
                }
        }
    };

    const int ktot = K / BK;
    load_stage(0, 0);
    asm volatile("cp.async.commit_group;\n");
    load_stage(1, 1);
    asm volatile("cp.async.commit_group;\n");

    int s_comp = 0, s_load = 2;
    for (int kt = 0; kt < ktot; kt++) {
        asm volatile("cp.async.wait_group 1;\n");
        __syncthreads();
        if (kt + 2 < ktot) load_stage(kt + 2, s_load);
        asm volatile("cp.async.commit_group;\n");
        compute_stage(s_comp);
        s_comp = (s_comp == GEMM_STAGES - 1) ? 0 : s_comp + 1;
        s_load = (s_load == GEMM_STAGES - 1) ? 0 : s_load + 1;
    }

    const int rbase = am0 + wr * 64;
    const int cbase = bn0 + wc * 32;
    #pragma unroll
    for (int mt = 0; mt < 4; mt++) {
        int r0 = rbase + mt * 16 + (lane >> 2);
        #pragma unroll
        for (int nt = 0; nt < 4; nt++) {
            int c = cbase + nt * 8 + (lane & 3) * 2;
            float b0 = bias[c], b1 = bias[c + 1];
            float v00 = acc[mt][nt][0] + b0, v01 = acc[mt][nt][1] + b1;
            float v10 = acc[mt][nt][2] + b0, v11 = acc[mt][nt][3] + b1;
            if (OUT_MODE == 0) {
                *(float2*)(C + (size_t)r0 * N + c) = make_float2(v00, v01);
                *(float2*)(C + (size_t)(r0 + 8) * N + c) = make_float2(v10, v11);
            } else {
                __nv_bfloat16 h00 = __float2bfloat16(v00);
                __nv_bfloat16 h01 = __float2bfloat16(v01);
                __nv_bfloat16 h10 = __float2bfloat16(v10);
                __nv_bfloat16 h11 = __float2bfloat16(v11);
                *(__nv_bfloat162*)(Ch + (size_t)r0 * N + c) = __nv_bfloat162(h00, h01);
                *(__nv_bfloat162*)(Ch + (size_t)(r0 + 8) * N + c) = __nv_bfloat162(h10, h11);
                *(__nv_bfloat162*)(Cl + (size_t)r0 * N + c) = __nv_bfloat162(
                    __float2bfloat16(v00 - __bfloat162float(h00)),
                    __float2bfloat16(v01 - __bfloat162float(h01)));
                *(__nv_bfloat162*)(Cl + (size_t)(r0 + 8) * N + c) = __nv_bfloat162(
                    __float2bfloat16(v10 - __bfloat162float(h10)),
                    __float2bfloat16(v11 - __bfloat162float(h11)));
            }
        }
    }
}

__global__ void __launch_bounds__(256, 2) gemm_qkv(
    const __nv_bfloat16* __restrict__ xh, const __nv_bfloat16* __restrict__ xl,
    const __nv_bfloat16* __restrict__ wqh, const __nv_bfloat16* __restrict__ wql,
    const __nv_bfloat16* __restrict__ wkh, const __nv_bfloat16* __restrict__ wkl,
    const __nv_bfloat16* __restrict__ wvh, const __nv_bfloat16* __restrict__ wvl,
    const float* __restrict__ bq, const float* __restrict__ bk,
    const float* __restrict__ bv,
    __nv_bfloat16* __restrict__ qh, __nv_bfloat16* __restrict__ ql,
    __nv_bfloat16* __restrict__ kh, __nv_bfloat16* __restrict__ kl,
    __nv_bfloat16* __restrict__ vh, __nv_bfloat16* __restrict__ vl)
{
    extern __shared__ __nv_bfloat16 sm[];
    const int bx = blockIdx.x;
    const int am0 = blockIdx.y * BM;
    if (bx < 16) {
        gemm_core<1>(xh, xl, wqh, wql, bq, nullptr, qh, ql,
                     D_MODEL, D_MODEL, am0, bx * BN, sm);
    } else if (bx < 20) {
        gemm_core<1>(xh, xl, wkh, wkl, bk, nullptr, kh, kl,
                     D_KV, D_MODEL, am0, (bx - 16) * BN, sm);
    } else {
        gemm_core<1>(xh, xl, wvh, wvl, bv, nullptr, vh, vl,
                     D_KV, D_MODEL, am0, (bx - 20) * BN, sm);
    }
}

__global__ void __launch_bounds__(256, 2) gemm_out(
    const __nv_bfloat16* __restrict__ ah, const __nv_bfloat16* __restrict__ al,
    const __nv_bfloat16* __restrict__ woh, const __nv_bfloat16* __restrict__ wol,
    const float* __restrict__ bo, float* __restrict__ out)
{
    extern __shared__ __nv_bfloat16 sm[];
    gemm_core<0>(ah, al, woh, wol, bo, out, nullptr, nullptr,
                 D_MODEL, D_MODEL, blockIdx.y * BM, blockIdx.x * BN, sm);
}

// ---------------------------------------------------------------------------
// Fused causal GQA attention (R13 version, unchanged): Br=64, Bc=32,
// 128 threads, 2 CTAs/SM, exp2-domain softmax.
// ---------------------------------------------------------------------------
#define KST 136
#define Q_ELEMS (64 * KST)
#define KV_ELEMS (32 * KST)
#define ATT_STAGE (4 * KV_ELEMS)
#define ATT_SMEM_BYTES ((2 * Q_ELEMS + 2 * ATT_STAGE) * 2)   // 104448

__global__ void __launch_bounds__(128, 2) attn_mma(
    const __nv_bfloat16* __restrict__ Qh, const __nv_bfloat16* __restrict__ Ql,
    const __nv_bfloat16* __restrict__ Kh, const __nv_bfloat16* __restrict__ Kl,
    const __nv_bfloat16* __restrict__ Vh, const __nv_bfloat16* __restrict__ Vl,
    __nv_bfloat16* __restrict__ Oh, __nv_bfloat16* __restrict__ Ol)
{
    extern __shared__ __nv_bfloat16 sm[];
    __nv_bfloat16* sQh = sm;
    __nv_bfloat16* sQl = sQh + Q_ELEMS;
    __nv_bfloat16* sKV = sQl + Q_ELEMS;

    const int qb = (int)gridDim.x - 1 - (int)blockIdx.x;
    const int h = blockIdx.y, bb = blockIdx.z;
    const int q0 = qb * 64;
    const int tid = threadIdx.x;
    const int lane = tid & 31;
    const int w = tid >> 5;

    const size_t qoff = (size_t)(bb * TSEQ + q0) * D_MODEL + h * DH;
    const size_t kvoff = (size_t)(bb * TSEQ) * D_KV + (h >> 2) * DH;

    #pragma unroll
    for (int i = 0; i < 8; i++) {
        int idx = tid + i * 128;
        int row = idx >> 4, ch = idx & 15;
        uint32_t d = smem_u32(sQh + row * KST + ch * 8);
        cp16(d, Qh + qoff + (size_t)row * D_MODEL + ch * 8);
        cp16(d + Q_ELEMS * 2, Ql + qoff + (size_t)row * D_MODEL + ch * 8);
    }
    asm volatile("cp.async.commit_group;\n");

    const int ntiles = 2 * qb + 2;

    auto load_kv = [&](int t, int s) {
        __nv_bfloat16* base = sKV + s * ATT_STAGE;
        const size_t goff = kvoff + (size_t)(t * 32) * D_KV;
        #pragma unroll
        for (int i = 0; i < 4; i++) {
            int idx = tid + i * 128;
            int row = idx >> 4, ch = idx & 15;
            uint32_t d = smem_u32(base + row * KST + ch * 8);
            size_t g = goff + (size_t)row * D_KV + ch * 8;
            cp16(d, Kh + g);
            cp16(d + KV_ELEMS * 2, Kl + g);
            cp16(d + 2 * KV_ELEMS * 2, Vh + g);
            cp16(d + 3 * KV_ELEMS * 2, Vl + g);
        }
        asm volatile("cp.async.commit_group;\n");
    };

    load_kv(0, 0);

    float oacc[16][4];
    #pragma unroll
    for (int nt = 0; nt < 16; nt++)
        #pragma unroll
        for (int e = 0; e < 4; e++) oacc[nt][e] = 0.f;
    float m0 = -1e30f, m1 = -1e30f, l0 = 0.f, l1 = 0.f;

    const int r0g = q0 + w * 16 + (lane >> 2);
    const int r1g = r0g + 8;
    const float scl2 = 0.08838834764831845f * 1.44269504088896340736f;

    for (int t = 0; t < ntiles; t++) {
        if (t + 1 < ntiles) {
            load_kv(t + 1, (t + 1) & 1);
            asm volatile("cp.async.wait_group 1;\n");
        } else {
            asm volatile("cp.async.wait_group 0;\n");
        }
        __syncthreads();

        const int s0 = t * 32;
        const bool warp_active = (s0 <= q0 + w * 16 + 15);
        if (warp_active) {
            __nv_bfloat16* base = sKV + (t & 1) * ATT_STAGE;
            __nv_bfloat16* bKh = base;
            __nv_bfloat16* bVh = base + 2 * KV_ELEMS;

            float sacc[4][4];
            #pragma unroll
            for (int nt = 0; nt < 4; nt++)
                #pragma unroll
                for (int e = 0; e < 4; e++) sacc[nt][e] = 0.f;

            #pragma unroll
            for (int kc = 0; kc < 8; kc++) {
                uint32_t qa_h[4], qa_l[4];
                {
                    int row = w * 16 + (lane & 15);
                    int col = kc * 16 + ((lane >> 4) << 3);
                    uint32_t a = smem_u32(sQh + row * KST + col);
                    ldsm4(qa_h, a);
                    ldsm4(qa_l, a + Q_ELEMS * 2);
                }
                uint32_t kb_h[2][4], kb_l[2][4];
                #pragma unroll
                for (int nb = 0; nb < 2; nb++) {
                    int row = nb * 16 + (lane & 15);
                    int col = kc * 16 + ((lane >> 4) << 3);
                    uint32_t a = smem_u32(bKh + row * KST + col);
                    ldsm4(kb_h[nb], a);
                    ldsm4(kb_l[nb], a + KV_ELEMS * 2);
                }
                #pragma unroll
                for (int t3 = 0; t3 < 3; t3++) {
                    const uint32_t* qa = (t3 == 2) ? qa_l : qa_h;
                    #pragma unroll
                    for (int nb = 0; nb < 2; nb++) {
                        const uint32_t* kb = (t3 == 1) ? kb_l[nb] : kb_h[nb];
                        mma16816(sacc[2 * nb], qa, kb[0], kb[2]);
                        mma16816(sacc[2 * nb + 1], qa, kb[1], kb[3]);
                    }
                }
            }

            const bool need_mask = (s0 + 31 > q0 + w * 16);
            #pragma unroll
            for (int nt = 0; nt < 4; nt++) {
                int cg2 = s0 + nt * 8 + (lane & 3) * 2;
                #pragma unroll
                for (int e = 0; e < 4; e++) sacc[nt][e] *= scl2;
                if (need_mask) {
                    if (cg2 > r0g)     sacc[nt][0] = -1e30f;
                    if (cg2 + 1 > r0g) sacc[nt][1] = -1e30f;
                    if (cg2 > r1g)     sacc[nt][2] = -1e30f;
                    if (cg2 + 1 > r1g) sacc[nt][3] = -1e30f;
                }
            }

            float mx0 = -1e30f, mx1 = -1e30f;
            #pragma unroll
            for (int nt = 0; nt < 4; nt++) {
                mx0 = fmaxf(mx0, fmaxf(sacc[nt][0], sacc[nt][1]));
                mx1 = fmaxf(mx1, fmaxf(sacc[nt][2], sacc[nt][3]));
            }
            mx0 = fmaxf(mx0, __shfl_xor_sync(0xffffffffu, mx0, 1));
            mx0 = fmaxf(mx0, __shfl_xor_sync(0xffffffffu, mx0, 2));
            mx1 = fmaxf(mx1, __shfl_xor_sync(0xffffffffu, mx1, 1));
            mx1 = fmaxf(mx1, __shfl_xor_sync(0xffffffffu, mx1, 2));
            float nm0 = fmaxf(m0, mx0), nm1 = fmaxf(m1, mx1);
            float a0 = exp2f(m0 - nm0), a1 = exp2f(m1 - nm1);

            float sum0 = 0.f, sum1 = 0.f;
            #pragma unroll
            for (int nt = 0; nt < 4; nt++) {
                sacc[nt][0] = exp2f(sacc[nt][0] - nm0);
                sacc[nt][1] = exp2f(sacc[nt][1] - nm0);
                sacc[nt][2] = exp2f(sacc[nt][2] - nm1);
                sacc[nt][3] = exp2f(sacc[nt][3] - nm1);
                sum0 += sacc[nt][0] + sacc[nt][1];
                sum1 += sacc[nt][2] + sacc[nt][3];
            }
            sum0 += __shfl_xor_sync(0xffffffffu, sum0, 1);
            sum0 += __shfl_xor_sync(0xffffffffu, sum0, 2);
            sum1 += __shfl_xor_sync(0xffffffffu, sum1, 1);
            sum1 += __shfl_xor_sync(0xffffffffu, sum1, 2);
            l0 = l0 * a0 + sum0;
            l1 = l1 * a1 + sum1;
            m0 = nm0;
            m1 = nm1;

            if (a0 != 1.0f || a1 != 1.0f) {
                #pragma unroll
                for (int nt = 0; nt < 16; nt++) {
                    oacc[nt][0] *= a0;
                    oacc[nt][1] *= a0;
                    oacc[nt][2] *= a1;
                    oacc[nt][3] *= a1;
                }
            }

            const int sub = lane >> 3, r = lane & 7;
            #pragma unroll
            for (int kc2 = 0; kc2 < 2; kc2++) {
                const int n0 = 2 * kc2, n1 = n0 + 1;
                uint32_t pah[4], pal[4];
                {
                    float p00 = sacc[n0][0], p01 = sacc[n0][1];
                    float p02 = sacc[n0][2], p03 = sacc[n0][3];
                    float p10 = sacc[n1][0], p11 = sacc[n1][1];
                    float p12 = sacc[n1][2], p13 = sacc[n1][3];
                    uint32_t h0 = pack_bf2(p00, p01), h1 = pack_bf2(p02, p03);
                    uint32_t h2 = pack_bf2(p10, p11), h3 = pack_bf2(p12, p13);
                    pah[0] = h0; pah[1] = h1; pah[2] = h2; pah[3] = h3;
                    __nv_bfloat162 t0 = *(__nv_bfloat162*)&h0;
                    __nv_bfloat162 t1 = *(__nv_bfloat162*)&h1;
                    __nv_bfloat162 t2 = *(__nv_bfloat162*)&h2;
                    __nv_bfloat162 t3v = *(__nv_bfloat162*)&h3;
                    pal[0] = pack_bf2(p00 - __bfloat162float(t0.x),
                                      p01 - __bfloat162float(t0.y));
                    pal[1] = pack_bf2(p02 - __bfloat162float(t1.x),
                                      p03 - __bfloat162float(t1.y));
                    pal[2] = pack_bf2(p10 - __bfloat162float(t2.x),
                                      p11 - __bfloat162float(t2.y));
                    pal[3] = pack_bf2(p12 - __bfloat162float(t3v.x),
                                      p13 - __bfloat162float(t3v.y));
                }
                #pragma unroll
                for (int np = 0; np < 4; np++) {
                    const int ntb0 = 2 * np, ntb1 = 2 * np + 1;
                    uint32_t vhA[4], vlA[4], vhB[4], vlB[4];
                    int row = kc2 * 16 + ((sub & 1) << 3) + r;
                    int colA = ntb0 * 16 + ((sub >> 1) << 3);
                    int colB = ntb1 * 16 + ((sub >> 1) << 3);
                    uint32_t aA = smem_u32(bVh + row * KST + colA);
                    uint32_t aB = smem_u32(bVh + row * KST + colB);
                    ldsm4t(vhA, aA);
                    ldsm4t(vlA, aA + KV_ELEMS * 2);
                    ldsm4t(vhB, aB);
                    ldsm4t(vlB, aB + KV_ELEMS * 2);
                    #pragma unroll
                    for (int t3 = 0; t3 < 3; t3++) {
                        const uint32_t* p = (t3 == 2) ? pal : pah;
                        const uint32_t* vA = (t3 == 1) ? vlA : vhA;
                        const uint32_t* vB = (t3 == 1) ? vlB : vhB;
                        mma16816(oacc[2 * ntb0], p, vA[0], vA[1]);
                        mma16816(oacc[2 * ntb0 + 1], p, vA[2], vA[3]);
                        mma16816(oacc[2 * ntb1], p, vB[0], vB[1]);
                        mma16816(oacc[2 * ntb1 + 1], p, vB[2], vB[3]);
                    }
                }
            }
        }
        __syncthreads();
    }

    float inv0 = 1.f / l0, inv1 = 1.f / l1;
    size_t row0 = qoff + (size_t)(w * 16 + (lane >> 2)) * D_MODEL;
    size_t row1 = row0 + (size_t)8 * D_MODEL;
    #pragma unroll
    for (int nt = 0; nt < 16; nt++) {
        int c = nt * 8 + (lane & 3) * 2;
        float v00 = oacc[nt][0] * inv0, v01 = oacc[nt][1] * inv0;
        float v10 = oacc[nt][2] * inv1, v11 = oacc[nt][3] * inv1;
        __nv_bfloat16 h00 = __float2bfloat16(v00);
        __nv_bfloat16 h01 = __float2bfloat16(v01);
        __nv_bfloat16 h10 = __float2bfloat16(v10);
        __nv_bfloat16 h11 = __float2bfloat16(v11);
        *(__nv_bfloat162*)(Oh + row0 + c) = __nv_bfloat162(h00, h01);
        *(__nv_bfloat162*)(Oh + row1 + c) = __nv_bfloat162(h10, h11);
        *(__nv_bfloat162*)(Ol + row0 + c) = __nv_bfloat162(
            __float2bfloat16(v00 - __bfloat162float(h00)),
            __float2bfloat16(v01 - __bfloat162float(h01)));
        *(__nv_bfloat162*)(Ol + row1 + c) = __nv_bfloat162(
            __float2bfloat16(v10 - __bfloat162float(h10)),
            __float2bfloat16(v11 - __bfloat162float(h11)));
    }
}

// ---------------------------------------------------------------------------
extern "C" void kernel_launch(void* const* d_in, const int* in_sizes, int n_in,
                              void* d_out, int out_size)
{
    const float* x  = (const float*)d_in[0];
    const float* Wq = (const float*)d_in[1];
    const float* bq = (const float*)d_in[2];
    const float* Wk = (const float*)d_in[3];
    const float* bk = (const float*)d_in[4];
    const float* Wv = (const float*)d_in[5];
    const float* bv = (const float*)d_in[6];
    const float* Wo = (const float*)d_in[7];
    const float* bo = (const float*)d_in[8];
    float* out = (float*)d_out;

    __nv_bfloat16 *xh, *xl, *wqh, *wql, *wkh, *wkl, *wvh, *wvl, *woh, *wol;
    __nv_bfloat16 *qh, *ql, *kh, *kl, *vh, *vl, *ah, *al;
    cudaGetSymbolAddress((void**)&xh, g_xh);
    cudaGetSymbolAddress((void**)&xl, g_xl);
    cudaGetSymbolAddress((void**)&wqh, g_wqh);
    cudaGetSymbolAddress((void**)&wql, g_wql);
    cudaGetSymbolAddress((void**)&wkh, g_wkh);
    cudaGetSymbolAddress((void**)&wkl, g_wkl);
    cudaGetSymbolAddress((void**)&wvh, g_wvh);
    cudaGetSymbolAddress((void**)&wvl, g_wvl);
    cudaGetSymbolAddress((void**)&woh, g_woh);
    cudaGetSymbolAddress((void**)&wol, g_wol);
    cudaGetSymbolAddress((void**)&qh, g_qh);
    cudaGetSymbolAddress((void**)&ql, g_ql);
    cudaGetSymbolAddress((void**)&kh, g_kh);
    cudaGetSymbolAddress((void**)&kl, g_kl);
    cudaGetSymbolAddress((void**)&vh, g_vh);
    cudaGetSymbolAddress((void**)&vl, g_vl);
    cudaGetSymbolAddress((void**)&ah, g_ah);
    cudaGetSymbolAddress((void**)&al, g_al);

    cudaFuncSetAttribute(gemm_qkv,
                         cudaFuncAttributeMaxDynamicSharedMemorySize,
                         GEMM_SMEM_BYTES);
    cudaFuncSetAttribute(gemm_out,
                         cudaFuncAttributeMaxDynamicSharedMemorySize,
                         GEMM_SMEM_BYTES);
    cudaFuncSetAttribute(attn_mma,
                         cudaFuncAttributeMaxDynamicSharedMemorySize,
                         ATT_SMEM_BYTES);

    // all splits in one launch (8 floats/thread)
    split_all<<<9216, 256>>>(x, Wq, Wk, Wv, Wo,
                             xh, xl, wqh, wql, wkh, wkl, wvh, wvl, woh, wol);

    // fused QKV projections -> bf16 hi/lo (128x128 tiles, 2 CTA/SM)
    gemm_qkv<<<dim3(24, MROWS / BM), 256, GEMM_SMEM_BYTES>>>(
        xh, xl, wqh, wql, wkh, wkl, wvh, wvl, bq, bk, bv,
        qh, ql, kh, kl, vh, vl);

    // fused causal GQA attention (Br=64, Bc=32, 2 CTAs/SM, exp2 softmax)
    attn_mma<<<dim3(TSEQ / 64, HQ, BATCH), 128, ATT_SMEM_BYTES>>>(
        qh, ql, kh, kl, vh, vl, ah, al);

    // output projection -> fp32 out
    gemm_out<<<dim3(D_MODEL / BN, MROWS / BM), 256, GEMM_SMEM_BYTES>>>(
        ah, al, woh, wol, bo, out);
}

// round 16
// speedup vs baseline: 1.5369x; 1.5369x over previous
#include <cuda_runtime.h>
#include <cuda_bf16.h>
#include <cstdint>

#define D_MODEL 2048
#define D_KV    512
#define HQ      16
#define DH      128
#define BATCH   2
#define TSEQ    2048
#define MROWS   (BATCH * TSEQ)   // 4096

// ---------------- scratch (__device__ globals; no allocation allowed) -------
__device__ __nv_bfloat16 g_xh[MROWS * D_MODEL];
__device__ __nv_bfloat16 g_xl[MROWS * D_MODEL];
__device__ __nv_bfloat16 g_wqh[D_MODEL * D_MODEL];
__device__ __nv_bfloat16 g_wql[D_MODEL * D_MODEL];
__device__ __nv_bfloat16 g_wkh[D_MODEL * D_KV];
__device__ __nv_bfloat16 g_wkl[D_MODEL * D_KV];
__device__ __nv_bfloat16 g_wvh[D_MODEL * D_KV];
__device__ __nv_bfloat16 g_wvl[D_MODEL * D_KV];
__device__ __nv_bfloat16 g_woh[D_MODEL * D_MODEL];
__device__ __nv_bfloat16 g_wol[D_MODEL * D_MODEL];

__device__ __nv_bfloat16 g_qh[MROWS * D_MODEL];
__device__ __nv_bfloat16 g_ql[MROWS * D_MODEL];
__device__ __nv_bfloat16 g_kh[MROWS * D_KV];
__device__ __nv_bfloat16 g_kl[MROWS * D_KV];
__device__ __nv_bfloat16 g_vh[MROWS * D_KV];
__device__ __nv_bfloat16 g_vl[MROWS * D_KV];
__device__ __nv_bfloat16 g_ah[MROWS * D_MODEL];
__device__ __nv_bfloat16 g_al[MROWS * D_MODEL];

// ---------------------------------------------------------------------------
// merged fp32 -> (bf16 hi, lo) split, 8 floats/thread.
// ---------------------------------------------------------------------------
__global__ void __launch_bounds__(256) split_all(
    const float* __restrict__ x,  const float* __restrict__ Wq,
    const float* __restrict__ Wk, const float* __restrict__ Wv,
    const float* __restrict__ Wo,
    __nv_bfloat16* __restrict__ xh,  __nv_bfloat16* __restrict__ xl,
    __nv_bfloat16* __restrict__ wqh, __nv_bfloat16* __restrict__ wql,
    __nv_bfloat16* __restrict__ wkh, __nv_bfloat16* __restrict__ wkl,
    __nv_bfloat16* __restrict__ wvh, __nv_bfloat16* __restrict__ wvl,
    __nv_bfloat16* __restrict__ woh, __nv_bfloat16* __restrict__ wol)
{
    const int b = blockIdx.x;
    const float* s;
    __nv_bfloat16 *hi, *lo;
    int base;
    if (b < 4096)      { s = x;  hi = xh;  lo = xl;  base = b; }
    else if (b < 6144) { s = Wq; hi = wqh; lo = wql; base = b - 4096; }
    else if (b < 6656) { s = Wk; hi = wkh; lo = wkl; base = b - 6144; }
    else if (b < 7168) { s = Wv; hi = wvh; lo = wvl; base = b - 6656; }
    else               { s = Wo; hi = woh; lo = wol; base = b - 7168; }

    #pragma unroll
    for (int u = 0; u < 2; u++) {
        size_t i = (size_t)base * 2048 + u * 1024 + threadIdx.x * 4;
        float4 v = *(const float4*)(s + i);
        float f[4] = {v.x, v.y, v.z, v.w};
        __nv_bfloat16 h[4], l[4];
        #pragma unroll
        for (int j = 0; j < 4; j++) {
            h[j] = __float2bfloat16(f[j]);
            l[j] = __float2bfloat16(f[j] - __bfloat162float(h[j]));
        }
        ((__nv_bfloat162*)(hi + i))[0] = __nv_bfloat162(h[0], h[1]);
        ((__nv_bfloat162*)(hi + i))[1] = __nv_bfloat162(h[2], h[3]);
        ((__nv_bfloat162*)(lo + i))[0] = __nv_bfloat162(l[0], l[1]);
        ((__nv_bfloat162*)(lo + i))[1] = __nv_bfloat162(l[2], l[3]);
    }
}

// ---------------------------------------------------------------------------
// helpers
// ---------------------------------------------------------------------------
__device__ __forceinline__ uint32_t smem_u32(const void* p) {
    return (uint32_t)__cvta_generic_to_shared(p);
}
__device__ __forceinline__ void cp16(uint32_t d, const void* s) {
    asm volatile("cp.async.cg.shared.global [%0], [%1], 16;\n" :: "r"(d), "l"(s));
}
__device__ __forceinline__ void ldsm4(uint32_t* r, uint32_t a) {
    asm volatile("ldmatrix.sync.aligned.m8n8.x4.shared.b16 {%0,%1,%2,%3}, [%4];"
        : "=r"(r[0]), "=r"(r[1]), "=r"(r[2]), "=r"(r[3]) : "r"(a));
}
__device__ __forceinline__ void ldsm4t(uint32_t* r, uint32_t a) {
    asm volatile("ldmatrix.sync.aligned.m8n8.x4.trans.shared.b16 {%0,%1,%2,%3}, [%4];"
        : "=r"(r[0]), "=r"(r[1]), "=r"(r[2]), "=r"(r[3]) : "r"(a));
}
__device__ __forceinline__ void mma16816(float* d, const uint32_t* a,
                                         uint32_t b0, uint32_t b1) {
    asm volatile(
        "mma.sync.aligned.m16n8k16.row.col.f32.bf16.bf16.f32 "
        "{%0,%1,%2,%3}, {%4,%5,%6,%7}, {%8,%9}, {%0,%1,%2,%3};"
        : "+f"(d[0]), "+f"(d[1]), "+f"(d[2]), "+f"(d[3])
        : "r"(a[0]), "r"(a[1]), "r"(a[2]), "r"(a[3]), "r"(b0), "r"(b1));
}
__device__ __forceinline__ uint32_t pack_bf2(float x, float y) {
    __nv_bfloat162 t(__float2bfloat16(x), __float2bfloat16(y));
    return *(uint32_t*)&t;
}

// ---------------------------------------------------------------------------
// GEMM core (R13 config): 2-term bf16 split, 128x128x32 tile, 3-stage
// cp.async pipeline, term-outer MMA ordering, 2 CTAs/SM.
// ---------------------------------------------------------------------------
#define BM 128
#define BN 128
#define BK 32
#define AST 40
#define BST 136
#define A_TILE (BM * AST)
#define B_TILE (BK * BST)
#define STAGE_ELEMS (2 * A_TILE + 2 * B_TILE)
#define GEMM_STAGES 3
#define GEMM_SMEM_BYTES (GEMM_STAGES * STAGE_ELEMS * 2)

template<int OUT_MODE>
__device__ __forceinline__ void gemm_core(
    const __nv_bfloat16* __restrict__ Ah, const __nv_bfloat16* __restrict__ Al,
    const __nv_bfloat16* __restrict__ Bh, const __nv_bfloat16* __restrict__ Bl,
    const float* __restrict__ bias, float* __restrict__ C,
    __nv_bfloat16* __restrict__ Ch, __nv_bfloat16* __restrict__ Cl,
    int N, int K, int am0, int bn0, __nv_bfloat16* sm)
{
    const int tid = threadIdx.x;
    const int lane = tid & 31;
    const int wid = tid >> 5;
    const int wr = wid >> 2;
    const int wc = wid & 3;

    float acc[4][4][4];
    #pragma unroll
    for (int mt = 0; mt < 4; mt++)
        #pragma unroll
        for (int nt = 0; nt < 4; nt++)
            #pragma unroll
            for (int e = 0; e < 4; e++) acc[mt][nt][e] = 0.f;

    auto load_stage = [&](int kt, int s) {
        const int k0 = kt * BK;
        __nv_bfloat16* base = sm + s * STAGE_ELEMS;
        #pragma unroll
        for (int i = 0; i < 2; i++) {
            int idx = tid + i * 256;
            int row = idx >> 2, ch = idx & 3;
            uint32_t d = smem_u32(base + row * AST + ch * 8);
            const size_t g = (size_t)(am0 + row) * K + k0 + ch * 8;
            cp16(d, Ah + g);
            cp16(d + A_TILE * 2, Al + g);
        }
        #pragma unroll
        for (int i = 0; i < 2; i++) {
            int idx = tid + i * 256;
            int row = idx >> 4, ch = idx & 15;
            uint32_t d = smem_u32(base + 2 * A_TILE + row * BST + ch * 8);
            const size_t g = (size_t)(k0 + row) * N + bn0 + ch * 8;
            cp16(d, Bh + g);
            cp16(d + B_TILE * 2, Bl + g);
        }
    };

    auto compute_stage = [&](int s) {
        __nv_bfloat16* base = sm + s * STAGE_ELEMS;
        const int sub = lane >> 3, r = lane & 7;
        #pragma unroll
        for (int ks = 0; ks < 2; ks++) {
            uint32_t ah[4][4], al[4][4], bh[2][4], bl[2][4];
            #pragma unroll
            for (int mt = 0; mt < 4; mt++) {
                int row = wr * 64 + mt * 16 + ((sub & 1) << 3) + r;
                int col = ks * 16 + ((sub >> 1) << 3);
                uint32_t a = smem_u32(base + row * AST + col);
                ldsm4(ah[mt], a);
                ldsm4(al[mt], a + A_TILE * 2);
            }
            #pragma unroll
            for (int ng = 0; ng < 2; ng++) {
                int krow = ks * 16 + ((sub & 1) << 3) + r;
                int ncol = wc * 32 + ng * 16 + ((sub >> 1) << 3);
                uint32_t b = smem_u32(base + 2 * A_TILE + krow * BST + ncol);
                ldsm4t(bh[ng], b);
                ldsm4t(bl[ng], b + B_TILE * 2);
            }
            #pragma unroll
            for (int t3 = 0; t3 < 3; t3++)
                #pragma unroll
                for (int mt = 0; mt < 4; mt++)
                    #pragma unroll
                    for (int nt = 0; nt < 4; nt++) {
                        int ng = nt >> 1, o = (nt & 1) * 2;
                        const uint32_t* a = (t3 == 2) ? al[mt] : ah[mt];
                        uint32_t b0 = (t3 == 1) ? bl[ng][o] : bh[ng][o];
                        uint32_t b1 = (t3 == 1) ? bl[ng][o + 1] : bh[ng][o + 1];
                        mma16816(acc[mt][nt], a, b0, b1);
                    }
        }
    };

    const int ktot = K / BK;
    load_stage(0, 0);
    asm volatile("cp.async.commit_group;\n");
    load_stage(1, 1);
    asm volatile("cp.async.commit_group;\n");

    int s_comp = 0, s_load = 2;
    for (int kt = 0; kt < ktot; kt++) {
        asm volatile("cp.async.wait_group 1;\n");
        __syncthreads();
        if (kt + 2 < ktot) load_stage(kt + 2, s_load);
        asm volatile("cp.async.commit_group;\n");
        compute_stage(s_comp);
        s_comp = (s_comp == GEMM_STAGES - 1) ? 0 : s_comp + 1;
        s_load = (s_load == GEMM_STAGES - 1) ? 0 : s_load + 1;
    }

    const int rbase = am0 + wr * 64;
    const int cbase = bn0 + wc * 32;
    #pragma unroll
    for (int mt = 0; mt < 4; mt++) {
        int r0 = rbase + mt * 16 + (lane >> 2);
        #pragma unroll
        for (int nt = 0; nt < 4; nt++) {
            int c = cbase + nt * 8 + (lane & 3) * 2;
            float b0 = bias[c], b1 = bias[c + 1];
            float v00 = acc[mt][nt][0] + b0, v01 = acc[mt][nt][1] + b1;
            float v10 = acc[mt][nt][2] + b0, v11 = acc[mt][nt][3] + b1;
            if (OUT_MODE == 0) {
                *(float2*)(C + (size_t)r0 * N + c) = make_float2(v00, v01);
                *(float2*)(C + (size_t)(r0 + 8) * N + c) = make_float2(v10, v11);
            } else {
                __nv_bfloat16 h00 = __float2bfloat16(v00);
                __nv_bfloat16 h01 = __float2bfloat16(v01);
                __nv_bfloat16 h10 = __float2bfloat16(v10);
                __nv_bfloat16 h11 = __float2bfloat16(v11);
                *(__nv_bfloat162*)(Ch + (size_t)r0 * N + c) = __nv_bfloat162(h00, h01);
                *(__nv_bfloat162*)(Ch + (size_t)(r0 + 8) * N + c) = __nv_bfloat162(h10, h11);
                *(__nv_bfloat162*)(Cl + (size_t)r0 * N + c) = __nv_bfloat162(
                    __float2bfloat16(v00 - __bfloat162float(h00)),
                    __float2bfloat16(v01 - __bfloat162float(h01)));
                *(__nv_bfloat162*)(Cl + (size_t)(r0 + 8) * N + c) = __nv_bfloat162(
                    __float2bfloat16(v10 - __bfloat162float(h10)),
                    __float2bfloat16(v11 - __bfloat162float(h11)));
            }
        }
    }
}

__global__ void __launch_bounds__(256, 2) gemm_qkv(
    const __nv_bfloat16* __restrict__ xh, const __nv_bfloat16* __restrict__ xl,
    const __nv_bfloat16* __restrict__ wqh, const __nv_bfloat16* __restrict__ wql,
    const __nv_bfloat16* __restrict__ wkh, const __nv_bfloat16* __restrict__ wkl,
    const __nv_bfloat16* __restrict__ wvh, const __nv_bfloat16* __restrict__ wvl,
    const float* __restrict__ bq, const float* __restrict__ bk,
    const float* __restrict__ bv,
    __nv_bfloat16* __restrict__ qh, __nv_bfloat16* __restrict__ ql,
    __nv_bfloat16* __restrict__ kh, __nv_bfloat16* __restrict__ kl,
    __nv_bfloat16* __restrict__ vh, __nv_bfloat16* __restrict__ vl)
{
    extern __shared__ __nv_bfloat16 sm[];
    const int bx = blockIdx.x;
    const int am0 = blockIdx.y * BM;
    if (bx < 16) {
        gemm_core<1>(xh, xl, wqh, wql, bq, nullptr, qh, ql,
                     D_MODEL, D_MODEL, am0, bx * BN, sm);
    } else if (bx < 20) {
        gemm_core<1>(xh, xl, wkh, wkl, bk, nullptr, kh, kl,
                     D_KV, D_MODEL, am0, (bx - 16) * BN, sm);
    } else {
        gemm_core<1>(xh, xl, wvh, wvl, bv, nullptr, vh, vl,
                     D_KV, D_MODEL, am0, (bx - 20) * BN, sm);
    }
}

__global__ void __launch_bounds__(256, 2) gemm_out(
    const __nv_bfloat16* __restrict__ ah, const __nv_bfloat16* __restrict__ al,
    const __nv_bfloat16* __restrict__ woh, const __nv_bfloat16* __restrict__ wol,
    const float* __restrict__ bo, float* __restrict__ out)
{
    extern __shared__ __nv_bfloat16 sm[];
    gemm_core<0>(ah, al, woh, wol, bo, out, nullptr, nullptr,
                 D_MODEL, D_MODEL, blockIdx.y * BM, blockIdx.x * BN, sm);
}

// ---------------------------------------------------------------------------
// Fused causal GQA attention (R13 version): Br=64, Bc=32, 128 threads,
// 2 CTAs/SM, exp2-domain softmax.
// ---------------------------------------------------------------------------
#define KST 136
#define Q_ELEMS (64 * KST)
#define KV_ELEMS (32 * KST)
#define ATT_STAGE (4 * KV_ELEMS)
#define ATT_SMEM_BYTES ((2 * Q_ELEMS + 2 * ATT_STAGE) * 2)   // 104448

__global__ void __launch_bounds__(128, 2) attn_mma(
    const __nv_bfloat16* __restrict__ Qh, const __nv_bfloat16* __restrict__ Ql,
    const __nv_bfloat16* __restrict__ Kh, const __nv_bfloat16* __restrict__ Kl,
    const __nv_bfloat16* __restrict__ Vh, const __nv_bfloat16* __restrict__ Vl,
    __nv_bfloat16* __restrict__ Oh, __nv_bfloat16* __restrict__ Ol)
{
    extern __shared__ __nv_bfloat16 sm[];
    __nv_bfloat16* sQh = sm;
    __nv_bfloat16* sQl = sQh + Q_ELEMS;
    __nv_bfloat16* sKV = sQl + Q_ELEMS;

    const int qb = (int)gridDim.x - 1 - (int)blockIdx.x;
    const int h = blockIdx.y, bb = blockIdx.z;
    const int q0 = qb * 64;
    const int tid = threadIdx.x;
    const int lane = tid & 31;
    const int w = tid >> 5;

    const size_t qoff = (size_t)(bb * TSEQ + q0) * D_MODEL + h * DH;
    const size_t kvoff = (size_t)(bb * TSEQ) * D_KV + (h >> 2) * DH;

    #pragma unroll
    for (int i = 0; i < 8; i++) {
        int idx = tid + i * 128;
        int row = idx >> 4, ch = idx & 15;
        uint32_t d = smem_u32(sQh + row * KST + ch * 8);
        cp16(d, Qh + qoff + (size_t)row * D_MODEL + ch * 8);
        cp16(d + Q_ELEMS * 2, Ql + qoff + (size_t)row * D_MODEL + ch * 8);
    }
    asm volatile("cp.async.commit_group;\n");

    const int ntiles = 2 * qb + 2;

    auto load_kv = [&](int t, int s) {
        __nv_bfloat16* base = sKV + s * ATT_STAGE;
        const size_t goff = kvoff + (size_t)(t * 32) * D_KV;
        #pragma unroll
        for (int i = 0; i < 4; i++) {
            int idx = tid + i * 128;
            int row = idx >> 4, ch = idx & 15;
            uint32_t d = smem_u32(base + row * KST + ch * 8);
            size_t g = goff + (size_t)row * D_KV + ch * 8;
            cp16(d, Kh + g);
            cp16(d + KV_ELEMS * 2, Kl + g);
            cp16(d + 2 * KV_ELEMS * 2, Vh + g);
            cp16(d + 3 * KV_ELEMS * 2, Vl + g);
        }
        asm volatile("cp.async.commit_group;\n");
    };

    load_kv(0, 0);

    float oacc[16][4];
    #pragma unroll
    for (int nt = 0; nt < 16; nt++)
        #pragma unroll
        for (int e = 0; e < 4; e++) oacc[nt][e] = 0.f;
    float m0 = -1e30f, m1 = -1e30f, l0 = 0.f, l1 = 0.f;

    const int r0g = q0 + w * 16 + (lane >> 2);
    const int r1g = r0g + 8;
    const float scl2 = 0.08838834764831845f * 1.44269504088896340736f;

    for (int t = 0; t < ntiles; t++) {
        if (t + 1 < ntiles) {
            load_kv(t + 1, (t + 1) & 1);
            asm volatile("cp.async.wait_group 1;\n");
        } else {
            asm volatile("cp.async.wait_group 0;\n");
        }
        __syncthreads();

        const int s0 = t * 32;
        const bool warp_active = (s0 <= q0 + w * 16 + 15);
        if (warp_active) {
            __nv_bfloat16* base = sKV + (t & 1) * ATT_STAGE;
            __nv_bfloat16* bKh = base;
            __nv_bfloat16* bVh = base + 2 * KV_ELEMS;

            float sacc[4][4];
            #pragma unroll
            for (int nt = 0; nt < 4; nt++)
                #pragma unroll
                for (int e = 0; e < 4; e++) sacc[nt][e] = 0.f;

            #pragma unroll
            for (int kc = 0; kc < 8; kc++) {
                uint32_t qa_h[4], qa_l[4];
                {
                    int row = w * 16 + (lane & 15);
                    int col = kc * 16 + ((lane >> 4) << 3);
                    uint32_t a = smem_u32(sQh + row * KST + col);
                    ldsm4(qa_h, a);
                    ldsm4(qa_l, a + Q_ELEMS * 2);
                }
                uint32_t kb_h[2][4], kb_l[2][4];
                #pragma unroll
                for (int nb = 0; nb < 2; nb++) {
                    int row = nb * 16 + (lane & 15);
                    int col = kc * 16 + ((lane >> 4) << 3);
                    uint32_t a = smem_u32(bKh + row * KST + col);
                    ldsm4(kb_h[nb], a);
                    ldsm4(kb_l[nb], a + KV_ELEMS * 2);
                }
                #pragma unroll
                for (int t3 = 0; t3 < 3; t3++) {
                    const uint32_t* qa = (t3 == 2) ? qa_l : qa_h;
                    #pragma unroll
                    for (int nb = 0; nb < 2; nb++) {
                        const uint32_t* kb = (t3 == 1) ? kb_l[nb] : kb_h[nb];
                        mma16816(sacc[2 * nb], qa, kb[0], kb[2]);
                        mma16816(sacc[2 * nb + 1], qa, kb[1], kb[3]);
                    }
                }
            }

            const bool need_mask = (s0 + 31 > q0 + w * 16);
            #pragma unroll
            for (int nt = 0; nt < 4; nt++) {
                int cg2 = s0 + nt * 8 + (lane & 3) * 2;
                #pragma unroll
                for (int e = 0; e < 4; e++) sacc[nt][e] *= scl2;
                if (need_mask) {
                    if (cg2 > r0g)     sacc[nt][0] = -1e30f;
                    if (cg2 + 1 > r0g) sacc[nt][1] = -1e30f;
                    if (cg2 > r1g)     sacc[nt][2] = -1e30f;
                    if (cg2 + 1 > r1g) sacc[nt][3] = -1e30f;
                }
            }

            float mx0 = -1e30f, mx1 = -1e30f;
            #pragma unroll
            for (int nt = 0; nt < 4; nt++) {
                mx0 = fmaxf(mx0, fmaxf(sacc[nt][0], sacc[nt][1]));
                mx1 = fmaxf(mx1, fmaxf(sacc[nt][2], sacc[nt][3]));
            }
            mx0 = fmaxf(mx0, __shfl_xor_sync(0xffffffffu, mx0, 1));
            mx0 = fmaxf(mx0, __shfl_xor_sync(0xffffffffu, mx0, 2));
            mx1 = fmaxf(mx1, __shfl_xor_sync(0xffffffffu, mx1, 1));
            mx1 = fmaxf(mx1, __shfl_xor_sync(0xffffffffu, mx1, 2));
            float nm0 = fmaxf(m0, mx0), nm1 = fmaxf(m1, mx1);
            float a0 = exp2f(m0 - nm0), a1 = exp2f(m1 - nm1);

            float sum0 = 0.f, sum1 = 0.f;
            #pragma unroll
            for (int nt = 0; nt < 4; nt++) {
                sacc[nt][0] = exp2f(sacc[nt][0] - nm0);
                sacc[nt][1] = exp2f(sacc[nt][1] - nm0);
                sacc[nt][2] = exp2f(sacc[nt][2] - nm1);
                sacc[nt][3] = exp2f(sacc[nt][3] - nm1);
                sum0 += sacc[nt][0] + sacc[nt][1];
                sum1 += sacc[nt][2] + sacc[nt][3];
            }
            sum0 += __shfl_xor_sync(0xffffffffu, sum0, 1);
            sum0 += __shfl_xor_sync(0xffffffffu, sum0, 2);
            sum1 += __shfl_xor_sync(0xffffffffu, sum1, 1);
            sum1 += __shfl_xor_sync(0xffffffffu, sum1, 2);
            l0 = l0 * a0 + sum0;
            l1 = l1 * a1 + sum1;
            m0 = nm0;
            m1 = nm1;

            if (a0 != 1.0f || a1 != 1.0f) {
                #pragma unroll
                for (int nt = 0; nt < 16; nt++) {
                    oacc[nt][0] *= a0;
                    oacc[nt][1] *= a0;
                    oacc[nt][2] *= a1;
                    oacc[nt][3] *= a1;
                }
            }

            const int sub = lane >> 3, r = lane & 7;
            #pragma unroll
            for (int kc2 = 0; kc2 < 2; kc2++) {
                const int n0 = 2 * kc2, n1 = n0 + 1;
                uint32_t pah[4], pal[4];
                {
                    float p00 = sacc[n0][0], p01 = sacc[n0][1];
                    float p02 = sacc[n0][2], p03 = sacc[n0][3];
                    float p10 = sacc[n1][0], p11 = sacc[n1][1];
                    float p12 = sacc[n1][2], p13 = sacc[n1][3];
                    uint32_t h0 = pack_bf2(p00, p01), h1 = pack_bf2(p02, p03);
                    uint32_t h2 = pack_bf2(p10, p11), h3 = pack_bf2(p12, p13);
                    pah[0] = h0; pah[1] = h1; pah[2] = h2; pah[3] = h3;
                    __nv_bfloat162 t0 = *(__nv_bfloat162*)&h0;
                    __nv_bfloat162 t1 = *(__nv_bfloat162*)&h1;
                    __nv_bfloat162 t2 = *(__nv_bfloat162*)&h2;
                    __nv_bfloat162 t3v = *(__nv_bfloat162*)&h3;
                    pal[0] = pack_bf2(p00 - __bfloat162float(t0.x),
                                      p01 - __bfloat162float(t0.y));
                    pal[1] = pack_bf2(p02 - __bfloat162float(t1.x),
                                      p03 - __bfloat162float(t1.y));
                    pal[2] = pack_bf2(p10 - __bfloat162float(t2.x),
                                      p11 - __bfloat162float(t2.y));
                    pal[3] = pack_bf2(p12 - __bfloat162float(t3v.x),
                                      p13 - __bfloat162float(t3v.y));
                }
                #pragma unroll
                for (int np = 0; np < 4; np++) {
                    const int ntb0 = 2 * np, ntb1 = 2 * np + 1;
                    uint32_t vhA[4], vlA[4], vhB[4], vlB[4];
                    int row = kc2 * 16 + ((sub & 1) << 3) + r;
                    int colA = ntb0 * 16 + ((sub >> 1) << 3);
                    int colB = ntb1 * 16 + ((sub >> 1) << 3);
                    uint32_t aA = smem_u32(bVh + row * KST + colA);
                    uint32_t aB = smem_u32(bVh + row * KST + colB);
                    ldsm4t(vhA, aA);
                    ldsm4t(vlA, aA + KV_ELEMS * 2);
                    ldsm4t(vhB, aB);
                    ldsm4t(vlB, aB + KV_ELEMS * 2);
                    #pragma unroll
                    for (int t3 = 0; t3 < 3; t3++) {
                        const uint32_t* p = (t3 == 2) ? pal : pah;
                        const uint32_t* vA = (t3 == 1) ? vlA : vhA;
                        const uint32_t* vB = (t3 == 1) ? vlB : vhB;
                        mma16816(oacc[2 * ntb0], p, vA[0], vA[1]);
                        mma16816(oacc[2 * ntb0 + 1], p, vA[2], vA[3]);
                        mma16816(oacc[2 * ntb1], p, vB[0], vB[1]);
                        mma16816(oacc[2 * ntb1 + 1], p, vB[2], vB[3]);
                    }
                }
            }
        }
        __syncthreads();
    }

    float inv0 = 1.f / l0, inv1 = 1.f / l1;
    size_t row0 = qoff + (size_t)(w * 16 + (lane >> 2)) * D_MODEL;
    size_t row1 = row0 + (size_t)8 * D_MODEL;
    #pragma unroll
    for (int nt = 0; nt < 16; nt++) {
        int c = nt * 8 + (lane & 3) * 2;
        float v00 = oacc[nt][0] * inv0, v01 = oacc[nt][1] * inv0;
        float v10 = oacc[nt][2] * inv1, v11 = oacc[nt][3] * inv1;
        __nv_bfloat16 h00 = __float2bfloat16(v00);
        __nv_bfloat16 h01 = __float2bfloat16(v01);
        __nv_bfloat16 h10 = __float2bfloat16(v10);
        __nv_bfloat16 h11 = __float2bfloat16(v11);
        *(__nv_bfloat162*)(Oh + row0 + c) = __nv_bfloat162(h00, h01);
        *(__nv_bfloat162*)(Oh + row1 + c) = __nv_bfloat162(h10, h11);
        *(__nv_bfloat162*)(Ol + row0 + c) = __nv_bfloat162(
            __float2bfloat16(v00 - __bfloat162float(h00)),
            __float2bfloat16(v01 - __bfloat162float(h01)));
        *(__nv_bfloat162*)(Ol + row1 + c) = __nv_bfloat162(
            __float2bfloat16(v10 - __bfloat162float(h10)),
            __float2bfloat16(v11 - __bfloat162float(h11)));
    }
}

// ---------------------------------------------------------------------------
extern "C" void kernel_launch(void* const* d_in, const int* in_sizes, int n_in,
                              void* d_out, int out_size)
{
    const float* x  = (const float*)d_in[0];
    const float* Wq = (const float*)d_in[1];
    const float* bq = (const float*)d_in[2];
    const float* Wk = (const float*)d_in[3];
    const float* bk = (const float*)d_in[4];
    const float* Wv = (const float*)d_in[5];
    const float* bv = (const float*)d_in[6];
    const float* Wo = (const float*)d_in[7];
    const float* bo = (const float*)d_in[8];
    float* out = (float*)d_out;

    __nv_bfloat16 *xh, *xl, *wqh, *wql, *wkh, *wkl, *wvh, *wvl, *woh, *wol;
    __nv_bfloat16 *qh, *ql, *kh, *kl, *vh, *vl, *ah, *al;
    cudaGetSymbolAddress((void**)&xh, g_xh);
    cudaGetSymbolAddress((void**)&xl, g_xl);
    cudaGetSymbolAddress((void**)&wqh, g_wqh);
    cudaGetSymbolAddress((void**)&wql, g_wql);
    cudaGetSymbolAddress((void**)&wkh, g_wkh);
    cudaGetSymbolAddress((void**)&wkl, g_wkl);
    cudaGetSymbolAddress((void**)&wvh, g_wvh);
    cudaGetSymbolAddress((void**)&wvl, g_wvl);
    cudaGetSymbolAddress((void**)&woh, g_woh);
    cudaGetSymbolAddress((void**)&wol, g_wol);
    cudaGetSymbolAddress((void**)&qh, g_qh);
    cudaGetSymbolAddress((void**)&ql, g_ql);
    cudaGetSymbolAddress((void**)&kh, g_kh);
    cudaGetSymbolAddress((void**)&kl, g_kl);
    cudaGetSymbolAddress((void**)&vh, g_vh);
    cudaGetSymbolAddress((void**)&vl, g_vl);
    cudaGetSymbolAddress((void**)&ah, g_ah);
    cudaGetSymbolAddress((void**)&al, g_al);

    cudaFuncSetAttribute(gemm_qkv,
                         cudaFuncAttributeMaxDynamicSharedMemorySize,
                         GEMM_SMEM_BYTES);
    cudaFuncSetAttribute(gemm_out,
                         cudaFuncAttributeMaxDynamicSharedMemorySize,
                         GEMM_SMEM_BYTES);
    cudaFuncSetAttribute(attn_mma,
                         cudaFuncAttributeMaxDynamicSharedMemorySize,
                         ATT_SMEM_BYTES);

    // all splits in one launch (8 floats/thread)
    split_all<<<9216, 256>>>(x, Wq, Wk, Wv, Wo,
                             xh, xl, wqh, wql, wkh, wkl, wvh, wvl, woh, wol);

    // fused QKV projections -> bf16 hi/lo (128x128 tiles, 2 CTA/SM)
    gemm_qkv<<<dim3(24, MROWS / BM), 256, GEMM_SMEM_BYTES>>>(
        xh, xl, wqh, wql, wkh, wkl, wvh, wvl, bq, bk, bv,
        qh, ql, kh, kl, vh, vl);

    // fused causal GQA attention (Br=64, Bc=32, 2 CTAs/SM, exp2 softmax)
    attn_mma<<<dim3(TSEQ / 64, HQ, BATCH), 128, ATT_SMEM_BYTES>>>(
        qh, ql, kh, kl, vh, vl, ah, al);

    // output projection -> fp32 out
    gemm_out<<<dim3(D_MODEL / BN, MROWS / BM), 256, GEMM_SMEM_BYTES>>>(
        ah, al, woh, wol, bo, out);
}

// round 17
// speedup vs baseline: 1.5601x; 1.0151x over previous
#include <cuda_runtime.h>
#include <cuda_bf16.h>
#include <cstdint>

#define D_MODEL 2048
#define D_KV    512
#define HQ      16
#define DH      128
#define BATCH   2
#define TSEQ    2048
#define MROWS   (BATCH * TSEQ)   // 4096

// ---------------- scratch (__device__ globals; no allocation allowed) -------
__device__ __nv_bfloat16 g_xh[MROWS * D_MODEL];
__device__ __nv_bfloat16 g_xl[MROWS * D_MODEL];
__device__ __nv_bfloat16 g_wqh[D_MODEL * D_MODEL];
__device__ __nv_bfloat16 g_wql[D_MODEL * D_MODEL];
__device__ __nv_bfloat16 g_wkh[D_MODEL * D_KV];
__device__ __nv_bfloat16 g_wkl[D_MODEL * D_KV];
__device__ __nv_bfloat16 g_wvh[D_MODEL * D_KV];
__device__ __nv_bfloat16 g_wvl[D_MODEL * D_KV];
__device__ __nv_bfloat16 g_woh[D_MODEL * D_MODEL];
__device__ __nv_bfloat16 g_wol[D_MODEL * D_MODEL];

__device__ __nv_bfloat16 g_qh[MROWS * D_MODEL];
__device__ __nv_bfloat16 g_ql[MROWS * D_MODEL];
__device__ __nv_bfloat16 g_kh[MROWS * D_KV];
__device__ __nv_bfloat16 g_kl[MROWS * D_KV];
__device__ __nv_bfloat16 g_vh[MROWS * D_KV];
__device__ __nv_bfloat16 g_vl[MROWS * D_KV];
__device__ __nv_bfloat16 g_ah[MROWS * D_MODEL];
__device__ __nv_bfloat16 g_al[MROWS * D_MODEL];

// ---------------------------------------------------------------------------
// merged fp32 -> (bf16 hi, lo) split, 8 floats/thread.
// ---------------------------------------------------------------------------
__global__ void __launch_bounds__(256) split_all(
    const float* __restrict__ x,  const float* __restrict__ Wq,
    const float* __restrict__ Wk, const float* __restrict__ Wv,
    const float* __restrict__ Wo,
    __nv_bfloat16* __restrict__ xh,  __nv_bfloat16* __restrict__ xl,
    __nv_bfloat16* __restrict__ wqh, __nv_bfloat16* __restrict__ wql,
    __nv_bfloat16* __restrict__ wkh, __nv_bfloat16* __restrict__ wkl,
    __nv_bfloat16* __restrict__ wvh, __nv_bfloat16* __restrict__ wvl,
    __nv_bfloat16* __restrict__ woh, __nv_bfloat16* __restrict__ wol)
{
    const int b = blockIdx.x;
    const float* s;
    __nv_bfloat16 *hi, *lo;
    int base;
    if (b < 4096)      { s = x;  hi = xh;  lo = xl;  base = b; }
    else if (b < 6144) { s = Wq; hi = wqh; lo = wql; base = b - 4096; }
    else if (b < 6656) { s = Wk; hi = wkh; lo = wkl; base = b - 6144; }
    else if (b < 7168) { s = Wv; hi = wvh; lo = wvl; base = b - 6656; }
    else               { s = Wo; hi = woh; lo = wol; base = b - 7168; }

    #pragma unroll
    for (int u = 0; u < 2; u++) {
        size_t i = (size_t)base * 2048 + u * 1024 + threadIdx.x * 4;
        float4 v = *(const float4*)(s + i);
        float f[4] = {v.x, v.y, v.z, v.w};
        __nv_bfloat16 h[4], l[4];
        #pragma unroll
        for (int j = 0; j < 4; j++) {
            h[j] = __float2bfloat16(f[j]);
            l[j] = __float2bfloat16(f[j] - __bfloat162float(h[j]));
        }
        ((__nv_bfloat162*)(hi + i))[0] = __nv_bfloat162(h[0], h[1]);
        ((__nv_bfloat162*)(hi + i))[1] = __nv_bfloat162(h[2], h[3]);
        ((__nv_bfloat162*)(lo + i))[0] = __nv_bfloat162(l[0], l[1]);
        ((__nv_bfloat162*)(lo + i))[1] = __nv_bfloat162(l[2], l[3]);
    }
}

// ---------------------------------------------------------------------------
// helpers
// ---------------------------------------------------------------------------
__device__ __forceinline__ uint32_t smem_u32(const void* p) {
    return (uint32_t)__cvta_generic_to_shared(p);
}
__device__ __forceinline__ void cp16(uint32_t d, const void* s) {
    asm volatile("cp.async.cg.shared.global [%0], [%1], 16;\n" :: "r"(d), "l"(s));
}
__device__ __forceinline__ void ldsm4(uint32_t* r, uint32_t a) {
    asm volatile("ldmatrix.sync.aligned.m8n8.x4.shared.b16 {%0,%1,%2,%3}, [%4];"
        : "=r"(r[0]), "=r"(r[1]), "=r"(r[2]), "=r"(r[3]) : "r"(a));
}
__device__ __forceinline__ void ldsm4t(uint32_t* r, uint32_t a) {
    asm volatile("ldmatrix.sync.aligned.m8n8.x4.trans.shared.b16 {%0,%1,%2,%3}, [%4];"
        : "=r"(r[0]), "=r"(r[1]), "=r"(r[2]), "=r"(r[3]) : "r"(a));
}
__device__ __forceinline__ void mma16816(float* d, const uint32_t* a,
                                         uint32_t b0, uint32_t b1) {
    asm volatile(
        "mma.sync.aligned.m16n8k16.row.col.f32.bf16.bf16.f32 "
        "{%0,%1,%2,%3}, {%4,%5,%6,%7}, {%8,%9}, {%0,%1,%2,%3};"
        : "+f"(d[0]), "+f"(d[1]), "+f"(d[2]), "+f"(d[3])
        : "r"(a[0]), "r"(a[1]), "r"(a[2]), "r"(a[3]), "r"(b0), "r"(b1));
}
__device__ __forceinline__ uint32_t pack_bf2(float x, float y) {
    __nv_bfloat162 t(__float2bfloat16(x), __float2bfloat16(y));
    return *(uint32_t*)&t;
}

// ---------------------------------------------------------------------------
// GEMM core: 2-term bf16 split, 128x128x32 tile, 3-stage cp.async pipeline,
// 2 CTAs/SM. Next-stage cp.async issuance moved AFTER the ks=0 fragment
// ldsm's so the ldsm latency overlaps load issuance instead of stacking.
// Commit-group accounting identical to R13/R16 (one commit per iteration).
// ---------------------------------------------------------------------------
#define BM 128
#define BN 128
#define BK 32
#define AST 40
#define BST 136
#define A_TILE (BM * AST)
#define B_TILE (BK * BST)
#define STAGE_ELEMS (2 * A_TILE + 2 * B_TILE)
#define GEMM_STAGES 3
#define GEMM_SMEM_BYTES (GEMM_STAGES * STAGE_ELEMS * 2)

template<int OUT_MODE>
__device__ __forceinline__ void gemm_core(
    const __nv_bfloat16* __restrict__ Ah, const __nv_bfloat16* __restrict__ Al,
    const __nv_bfloat16* __restrict__ Bh, const __nv_bfloat16* __restrict__ Bl,
    const float* __restrict__ bias, float* __restrict__ C,
    __nv_bfloat16* __restrict__ Ch, __nv_bfloat16* __restrict__ Cl,
    int N, int K, int am0, int bn0, __nv_bfloat16* sm)
{
    const int tid = threadIdx.x;
    const int lane = tid & 31;
    const int wid = tid >> 5;
    const int wr = wid >> 2;
    const int wc = wid & 3;

    float acc[4][4][4];
    #pragma unroll
    for (int mt = 0; mt < 4; mt++)
        #pragma unroll
        for (int nt = 0; nt < 4; nt++)
            #pragma unroll
            for (int e = 0; e < 4; e++) acc[mt][nt][e] = 0.f;

    auto load_stage = [&](int kt, int s) {
        const int k0 = kt * BK;
        __nv_bfloat16* base = sm + s * STAGE_ELEMS;
        #pragma unroll
        for (int i = 0; i < 2; i++) {
            int idx = tid + i * 256;
            int row = idx >> 2, ch = idx & 3;
            uint32_t d = smem_u32(base + row * AST + ch * 8);
            const size_t g = (size_t)(am0 + row) * K + k0 + ch * 8;
            cp16(d, Ah + g);
            cp16(d + A_TILE * 2, Al + g);
        }
        #pragma unroll
        for (int i = 0; i < 2; i++) {
            int idx = tid + i * 256;
            int row = idx >> 4, ch = idx & 15;
            uint32_t d = smem_u32(base + 2 * A_TILE + row * BST + ch * 8);
            const size_t g = (size_t)(k0 + row) * N + bn0 + ch * 8;
            cp16(d, Bh + g);
            cp16(d + B_TILE * 2, Bl + g);
        }
    };

    // compute stage s; after the ks=0 fragment loads, issue next-stage
    // cp.asyncs (if any) and commit exactly once.
    auto compute_stage = [&](int s, bool do_load, int kt2, int sl) {
        __nv_bfloat16* base = sm + s * STAGE_ELEMS;
        const int sub = lane >> 3, r = lane & 7;
        #pragma unroll
        for (int ks = 0; ks < 2; ks++) {
            uint32_t ah[4][4], al[4][4], bh[2][4], bl[2][4];
            #pragma unroll
            for (int mt = 0; mt < 4; mt++) {
                int row = wr * 64 + mt * 16 + ((sub & 1) << 3) + r;
                int col = ks * 16 + ((sub >> 1) << 3);
                uint32_t a = smem_u32(base + row * AST + col);
                ldsm4(ah[mt], a);
                ldsm4(al[mt], a + A_TILE * 2);
            }
            #pragma unroll
            for (int ng = 0; ng < 2; ng++) {
                int krow = ks * 16 + ((sub & 1) << 3) + r;
                int ncol = wc * 32 + ng * 16 + ((sub >> 1) << 3);
                uint32_t b = smem_u32(base + 2 * A_TILE + krow * BST + ncol);
                ldsm4t(bh[ng], b);
                ldsm4t(bl[ng], b + B_TILE * 2);
            }
            if (ks == 0) {
                if (do_load) load_stage(kt2, sl);
                asm volatile("cp.async.commit_group;\n");
            }
            #pragma unroll
            for (int t3 = 0; t3 < 3; t3++)
                #pragma unroll
                for (int mt = 0; mt < 4; mt++)
                    #pragma unroll
                    for (int nt = 0; nt < 4; nt++) {
                        int ng = nt >> 1, o = (nt & 1) * 2;
                        const uint32_t* a = (t3 == 2) ? al[mt] : ah[mt];
                        uint32_t b0 = (t3 == 1) ? bl[ng][o] : bh[ng][o];
                        uint32_t b1 = (t3 == 1) ? bl[ng][o + 1] : bh[ng][o + 1];
                        mma16816(acc[mt][nt], a, b0, b1);
                    }
        }
    };

    const int ktot = K / BK;
    load_stage(0, 0);
    asm volatile("cp.async.commit_group;\n");
    load_stage(1, 1);
    asm volatile("cp.async.commit_group;\n");

    int s_comp = 0, s_load = 2;
    for (int kt = 0; kt < ktot; kt++) {
        asm volatile("cp.async.wait_group 1;\n");
        __syncthreads();
        compute_stage(s_comp, kt + 2 < ktot, kt + 2, s_load);
        s_comp = (s_comp == GEMM_STAGES - 1) ? 0 : s_comp + 1;
        s_load = (s_load == GEMM_STAGES - 1) ? 0 : s_load + 1;
    }

    const int rbase = am0 + wr * 64;
    const int cbase = bn0 + wc * 32;
    #pragma unroll
    for (int mt = 0; mt < 4; mt++) {
        int r0 = rbase + mt * 16 + (lane >> 2);
        #pragma unroll
        for (int nt = 0; nt < 4; nt++) {
            int c = cbase + nt * 8 + (lane & 3) * 2;
            float b0 = bias[c], b1 = bias[c + 1];
            float v00 = acc[mt][nt][0] + b0, v01 = acc[mt][nt][1] + b1;
            float v10 = acc[mt][nt][2] + b0, v11 = acc[mt][nt][3] + b1;
            if (OUT_MODE == 0) {
                *(float2*)(C + (size_t)r0 * N + c) = make_float2(v00, v01);
                *(float2*)(C + (size_t)(r0 + 8) * N + c) = make_float2(v10, v11);
            } else {
                __nv_bfloat16 h00 = __float2bfloat16(v00);
                __nv_bfloat16 h01 = __float2bfloat16(v01);
                __nv_bfloat16 h10 = __float2bfloat16(v10);
                __nv_bfloat16 h11 = __float2bfloat16(v11);
                *(__nv_bfloat162*)(Ch + (size_t)r0 * N + c) = __nv_bfloat162(h00, h01);
                *(__nv_bfloat162*)(Ch + (size_t)(r0 + 8) * N + c) = __nv_bfloat162(h10, h11);
                *(__nv_bfloat162*)(Cl + (size_t)r0 * N + c) = __nv_bfloat162(
                    __float2bfloat16(v00 - __bfloat162float(h00)),
                    __float2bfloat16(v01 - __bfloat162float(h01)));
                *(__nv_bfloat162*)(Cl + (size_t)(r0 + 8) * N + c) = __nv_bfloat162(
                    __float2bfloat16(v10 - __bfloat162float(h10)),
                    __float2bfloat16(v11 - __bfloat162float(h11)));
            }
        }
    }
}

__global__ void __launch_bounds__(256, 2) gemm_qkv(
    const __nv_bfloat16* __restrict__ xh, const __nv_bfloat16* __restrict__ xl,
    const __nv_bfloat16* __restrict__ wqh, const __nv_bfloat16* __restrict__ wql,
    const __nv_bfloat16* __restrict__ wkh, const __nv_bfloat16* __restrict__ wkl,
    const __nv_bfloat16* __restrict__ wvh, const __nv_bfloat16* __restrict__ wvl,
    const float* __restrict__ bq, const float* __restrict__ bk,
    const float* __restrict__ bv,
    __nv_bfloat16* __restrict__ qh, __nv_bfloat16* __restrict__ ql,
    __nv_bfloat16* __restrict__ kh, __nv_bfloat16* __restrict__ kl,
    __nv_bfloat16* __restrict__ vh, __nv_bfloat16* __restrict__ vl)
{
    extern __shared__ __nv_bfloat16 sm[];
    const int bx = blockIdx.x;
    const int am0 = blockIdx.y * BM;
    if (bx < 16) {
        gemm_core<1>(xh, xl, wqh, wql, bq, nullptr, qh, ql,
                     D_MODEL, D_MODEL, am0, bx * BN, sm);
    } else if (bx < 20) {
        gemm_core<1>(xh, xl, wkh, wkl, bk, nullptr, kh, kl,
                     D_KV, D_MODEL, am0, (bx - 16) * BN, sm);
    } else {
        gemm_core<1>(xh, xl, wvh, wvl, bv, nullptr, vh, vl,
                     D_KV, D_MODEL, am0, (bx - 20) * BN, sm);
    }
}

__global__ void __launch_bounds__(256, 2) gemm_out(
    const __nv_bfloat16* __restrict__ ah, const __nv_bfloat16* __restrict__ al,
    const __nv_bfloat16* __restrict__ woh, const __nv_bfloat16* __restrict__ wol,
    const float* __restrict__ bo, float* __restrict__ out)
{
    extern __shared__ __nv_bfloat16 sm[];
    gemm_core<0>(ah, al, woh, wol, bo, out, nullptr, nullptr,
                 D_MODEL, D_MODEL, blockIdx.y * BM, blockIdx.x * BN, sm);
}

// ---------------------------------------------------------------------------
// Fused causal GQA attention (R13/R16 version, unchanged): Br=64, Bc=32,
// 128 threads, 2 CTAs/SM, exp2-domain softmax.
// ---------------------------------------------------------------------------
#define KST 136
#define Q_ELEMS (64 * KST)
#define KV_ELEMS (32 * KST)
#define ATT_STAGE (4 * KV_ELEMS)
#define ATT_SMEM_BYTES ((2 * Q_ELEMS + 2 * ATT_STAGE) * 2)   // 104448

__global__ void __launch_bounds__(128, 2) attn_mma(
    const __nv_bfloat16* __restrict__ Qh, const __nv_bfloat16* __restrict__ Ql,
    const __nv_bfloat16* __restrict__ Kh, const __nv_bfloat16* __restrict__ Kl,
    const __nv_bfloat16* __restrict__ Vh, const __nv_bfloat16* __restrict__ Vl,
    __nv_bfloat16* __restrict__ Oh, __nv_bfloat16* __restrict__ Ol)
{
    extern __shared__ __nv_bfloat16 sm[];
    __nv_bfloat16* sQh = sm;
    __nv_bfloat16* sQl = sQh + Q_ELEMS;
    __nv_bfloat16* sKV = sQl + Q_ELEMS;

    const int qb = (int)gridDim.x - 1 - (int)blockIdx.x;
    const int h = blockIdx.y, bb = blockIdx.z;
    const int q0 = qb * 64;
    const int tid = threadIdx.x;
    const int lane = tid & 31;
    const int w = tid >> 5;

    const size_t qoff = (size_t)(bb * TSEQ + q0) * D_MODEL + h * DH;
    const size_t kvoff = (size_t)(bb * TSEQ) * D_KV + (h >> 2) * DH;

    #pragma unroll
    for (int i = 0; i < 8; i++) {
        int idx = tid + i * 128;
        int row = idx >> 4, ch = idx & 15;
        uint32_t d = smem_u32(sQh + row * KST + ch * 8);
        cp16(d, Qh + qoff + (size_t)row * D_MODEL + ch * 8);
        cp16(d + Q_ELEMS * 2, Ql + qoff + (size_t)row * D_MODEL + ch * 8);
    }
    asm volatile("cp.async.commit_group;\n");

    const int ntiles = 2 * qb + 2;

    auto load_kv = [&](int t, int s) {
        __nv_bfloat16* base = sKV + s * ATT_STAGE;
        const size_t goff = kvoff + (size_t)(t * 32) * D_KV;
        #pragma unroll
        for (int i = 0; i < 4; i++) {
            int idx = tid + i * 128;
            int row = idx >> 4, ch = idx & 15;
            uint32_t d = smem_u32(base + row * KST + ch * 8);
            size_t g = goff + (size_t)row * D_KV + ch * 8;
            cp16(d, Kh + g);
            cp16(d + KV_ELEMS * 2, Kl + g);
            cp16(d + 2 * KV_ELEMS * 2, Vh + g);
            cp16(d + 3 * KV_ELEMS * 2, Vl + g);
        }
        asm volatile("cp.async.commit_group;\n");
    };

    load_kv(0, 0);

    float oacc[16][4];
    #pragma unroll
    for (int nt = 0; nt < 16; nt++)
        #pragma unroll
        for (int e = 0; e < 4; e++) oacc[nt][e] = 0.f;
    float m0 = -1e30f, m1 = -1e30f, l0 = 0.f, l1 = 0.f;

    const int r0g = q0 + w * 16 + (lane >> 2);
    const int r1g = r0g + 8;
    const float scl2 = 0.08838834764831845f * 1.44269504088896340736f;

    for (int t = 0; t < ntiles; t++) {
        if (t + 1 < ntiles) {
            load_kv(t + 1, (t + 1) & 1);
            asm volatile("cp.async.wait_group 1;\n");
        } else {
            asm volatile("cp.async.wait_group 0;\n");
        }
        __syncthreads();

        const int s0 = t * 32;
        const bool warp_active = (s0 <= q0 + w * 16 + 15);
        if (warp_active) {
            __nv_bfloat16* base = sKV + (t & 1) * ATT_STAGE;
            __nv_bfloat16* bKh = base;
            __nv_bfloat16* bVh = base + 2 * KV_ELEMS;

            float sacc[4][4];
            #pragma unroll
            for (int nt = 0; nt < 4; nt++)
                #pragma unroll
                for (int e = 0; e < 4; e++) sacc[nt][e] = 0.f;

            #pragma unroll
            for (int kc = 0; kc < 8; kc++) {
                uint32_t qa_h[4], qa_l[4];
                {
                    int row = w * 16 + (lane & 15);
                    int col = kc * 16 + ((lane >> 4) << 3);
                    uint32_t a = smem_u32(sQh + row * KST + col);
                    ldsm4(qa_h, a);
                    ldsm4(qa_l, a + Q_ELEMS * 2);
                }
                uint32_t kb_h[2][4], kb_l[2][4];
                #pragma unroll
                for (int nb = 0; nb < 2; nb++) {
                    int row = nb * 16 + (lane & 15);
                    int col = kc * 16 + ((lane >> 4) << 3);
                    uint32_t a = smem_u32(bKh + row * KST + col);
                    ldsm4(kb_h[nb], a);
                    ldsm4(kb_l[nb], a + KV_ELEMS * 2);
                }
                #pragma unroll
                for (int t3 = 0; t3 < 3; t3++) {
                    const uint32_t* qa = (t3 == 2) ? qa_l : qa_h;
                    #pragma unroll
                    for (int nb = 0; nb < 2; nb++) {
                        const uint32_t* kb = (t3 == 1) ? kb_l[nb] : kb_h[nb];
                        mma16816(sacc[2 * nb], qa, kb[0], kb[2]);
                        mma16816(sacc[2 * nb + 1], qa, kb[1], kb[3]);
                    }
                }
            }

            const bool need_mask = (s0 + 31 > q0 + w * 16);
            #pragma unroll
            for (int nt = 0; nt < 4; nt++) {
                int cg2 = s0 + nt * 8 + (lane & 3) * 2;
                #pragma unroll
                for (int e = 0; e < 4; e++) sacc[nt][e] *= scl2;
                if (need_mask) {
                    if (cg2 > r0g)     sacc[nt][0] = -1e30f;
                    if (cg2 + 1 > r0g) sacc[nt][1] = -1e30f;
                    if (cg2 > r1g)     sacc[nt][2] = -1e30f;
                    if (cg2 + 1 > r1g) sacc[nt][3] = -1e30f;
                }
            }

            float mx0 = -1e30f, mx1 = -1e30f;
            #pragma unroll
            for (int nt = 0; nt < 4; nt++) {
                mx0 = fmaxf(mx0, fmaxf(sacc[nt][0], sacc[nt][1]));
                mx1 = fmaxf(mx1, fmaxf(sacc[nt][2], sacc[nt][3]));
            }
            mx0 = fmaxf(mx0, __shfl_xor_sync(0xffffffffu, mx0, 1));
            mx0 = fmaxf(mx0, __shfl_xor_sync(0xffffffffu, mx0, 2));
            mx1 = fmaxf(mx1, __shfl_xor_sync(0xffffffffu, mx1, 1));
            mx1 = fmaxf(mx1, __shfl_xor_sync(0xffffffffu, mx1, 2));
            float nm0 = fmaxf(m0, mx0), nm1 = fmaxf(m1, mx1);
            float a0 = exp2f(m0 - nm0), a1 = exp2f(m1 - nm1);

            float sum0 = 0.f, sum1 = 0.f;
            #pragma unroll
            for (int nt = 0; nt < 4; nt++) {
                sacc[nt][0] = exp2f(sacc[nt][0] - nm0);
                sacc[nt][1] = exp2f(sacc[nt][1] - nm0);
                sacc[nt][2] = exp2f(sacc[nt][2] - nm1);
                sacc[nt][3] = exp2f(sacc[nt][3] - nm1);
                sum0 += sacc[nt][0] + sacc[nt][1];
                sum1 += sacc[nt][2] + sacc[nt][3];
            }
            sum0 += __shfl_xor_sync(0xffffffffu, sum0, 1);
            sum0 += __shfl_xor_sync(0xffffffffu, sum0, 2);
            sum1 += __shfl_xor_sync(0xffffffffu, sum1, 1);
            sum1 += __shfl_xor_sync(0xffffffffu, sum1, 2);
            l0 = l0 * a0 + sum0;
            l1 = l1 * a1 + sum1;
            m0 = nm0;
            m1 = nm1;

            if (a0 != 1.0f || a1 != 1.0f) {
                #pragma unroll
                for (int nt = 0; nt < 16; nt++) {
                    oacc[nt][0] *= a0;
                    oacc[nt][1] *= a0;
                    oacc[nt][2] *= a1;
                    oacc[nt][3] *= a1;
                }
            }

            const int sub = lane >> 3, r = lane & 7;
            #pragma unroll
            for (int kc2 = 0; kc2 < 2; kc2++) {
                const int n0 = 2 * kc2, n1 = n0 + 1;
                uint32_t pah[4], pal[4];
                {
                    float p00 = sacc[n0][0], p01 = sacc[n0][1];
                    float p02 = sacc[n0][2], p03 = sacc[n0][3];
                    float p10 = sacc[n1][0], p11 = sacc[n1][1];
                    float p12 = sacc[n1][2], p13 = sacc[n1][3];
                    uint32_t h0 = pack_bf2(p00, p01), h1 = pack_bf2(p02, p03);
                    uint32_t h2 = pack_bf2(p10, p11), h3 = pack_bf2(p12, p13);
                    pah[0] = h0; pah[1] = h1; pah[2] = h2; pah[3] = h3;
                    __nv_bfloat162 t0 = *(__nv_bfloat162*)&h0;
                    __nv_bfloat162 t1 = *(__nv_bfloat162*)&h1;
                    __nv_bfloat162 t2 = *(__nv_bfloat162*)&h2;
                    __nv_bfloat162 t3v = *(__nv_bfloat162*)&h3;
                    pal[0] = pack_bf2(p00 - __bfloat162float(t0.x),
                                      p01 - __bfloat162float(t0.y));
                    pal[1] = pack_bf2(p02 - __bfloat162float(t1.x),
                                      p03 - __bfloat162float(t1.y));
                    pal[2] = pack_bf2(p10 - __bfloat162float(t2.x),
                                      p11 - __bfloat162float(t2.y));
                    pal[3] = pack_bf2(p12 - __bfloat162float(t3v.x),
                                      p13 - __bfloat162float(t3v.y));
                }
                #pragma unroll
                for (int np = 0; np < 4; np++) {
                    const int ntb0 = 2 * np, ntb1 = 2 * np + 1;
                    uint32_t vhA[4], vlA[4], vhB[4], vlB[4];
                    int row = kc2 * 16 + ((sub & 1) << 3) + r;
                    int colA = ntb0 * 16 + ((sub >> 1) << 3);
                    int colB = ntb1 * 16 + ((sub >> 1) << 3);
                    uint32_t aA = smem_u32(bVh + row * KST + colA);
                    uint32_t aB = smem_u32(bVh + row * KST + colB);
                    ldsm4t(vhA, aA);
                    ldsm4t(vlA, aA + KV_ELEMS * 2);
                    ldsm4t(vhB, aB);
                    ldsm4t(vlB, aB + KV_ELEMS * 2);
                    #pragma unroll
                    for (int t3 = 0; t3 < 3; t3++) {
                        const uint32_t* p = (t3 == 2) ? pal : pah;
                        const uint32_t* vA = (t3 == 1) ? vlA : vhA;
                        const uint32_t* vB = (t3 == 1) ? vlB : vhB;
                        mma16816(oacc[2 * ntb0], p, vA[0], vA[1]);
                        mma16816(oacc[2 * ntb0 + 1], p, vA[2], vA[3]);
                        mma16816(oacc[2 * ntb1], p, vB[0], vB[1]);
                        mma16816(oacc[2 * ntb1 + 1], p, vB[2], vB[3]);
                    }
                }
            }
        }
        __syncthreads();
    }

    float inv0 = 1.f / l0, inv1 = 1.f / l1;
    size_t row0 = qoff + (size_t)(w * 16 + (lane >> 2)) * D_MODEL;
    size_t row1 = row0 + (size_t)8 * D_MODEL;
    #pragma unroll
    for (int nt = 0; nt < 16; nt++) {
        int c = nt * 8 + (lane & 3) * 2;
        float v00 = oacc[nt][0] * inv0, v01 = oacc[nt][1] * inv0;
        float v10 = oacc[nt][2] * inv1, v11 = oacc[nt][3] * inv1;
        __nv_bfloat16 h00 = __float2bfloat16(v00);
        __nv_bfloat16 h01 = __float2bfloat16(v01);
        __nv_bfloat16 h10 = __float2bfloat16(v10);
        __nv_bfloat16 h11 = __float2bfloat16(v11);
        *(__nv_bfloat162*)(Oh + row0 + c) = __nv_bfloat162(h00, h01);
        *(__nv_bfloat162*)(Oh + row1 + c) = __nv_bfloat162(h10, h11);
        *(__nv_bfloat162*)(Ol + row0 + c) = __nv_bfloat162(
            __float2bfloat16(v00 - __bfloat162float(h00)),
            __float2bfloat16(v01 - __bfloat162float(h01)));
        *(__nv_bfloat162*)(Ol + row1 + c) = __nv_bfloat162(
            __float2bfloat16(v10 - __bfloat162float(h10)),
            __float2bfloat16(v11 - __bfloat162float(h11)));
    }
}

// ---------------------------------------------------------------------------
extern "C" void kernel_launch(void* const* d_in, const int* in_sizes, int n_in,
                              void* d_out, int out_size)
{
    const float* x  = (const float*)d_in[0];
    const float* Wq = (const float*)d_in[1];
    const float* bq = (const float*)d_in[2];
    const float* Wk = (const float*)d_in[3];
    const float* bk = (const float*)d_in[4];
    const float* Wv = (const float*)d_in[5];
    const float* bv = (const float*)d_in[6];
    const float* Wo = (const float*)d_in[7];
    const float* bo = (const float*)d_in[8];
    float* out = (float*)d_out;

    __nv_bfloat16 *xh, *xl, *wqh, *wql, *wkh, *wkl, *wvh, *wvl, *woh, *wol;
    __nv_bfloat16 *qh, *ql, *kh, *kl, *vh, *vl, *ah, *al;
    cudaGetSymbolAddress((void**)&xh, g_xh);
    cudaGetSymbolAddress((void**)&xl, g_xl);
    cudaGetSymbolAddress((void**)&wqh, g_wqh);
    cudaGetSymbolAddress((void**)&wql, g_wql);
    cudaGetSymbolAddress((void**)&wkh, g_wkh);
    cudaGetSymbolAddress((void**)&wkl, g_wkl);
    cudaGetSymbolAddress((void**)&wvh, g_wvh);
    cudaGetSymbolAddress((void**)&wvl, g_wvl);
    cudaGetSymbolAddress((void**)&woh, g_woh);
    cudaGetSymbolAddress((void**)&wol, g_wol);
    cudaGetSymbolAddress((void**)&qh, g_qh);
    cudaGetSymbolAddress((void**)&ql, g_ql);
    cudaGetSymbolAddress((void**)&kh, g_kh);
    cudaGetSymbolAddress((void**)&kl, g_kl);
    cudaGetSymbolAddress((void**)&vh, g_vh);
    cudaGetSymbolAddress((void**)&vl, g_vl);
    cudaGetSymbolAddress((void**)&ah, g_ah);
    cudaGetSymbolAddress((void**)&al, g_al);

    cudaFuncSetAttribute(gemm_qkv,
                         cudaFuncAttributeMaxDynamicSharedMemorySize,
                         GEMM_SMEM_BYTES);
    cudaFuncSetAttribute(gemm_out,
                         cudaFuncAttributeMaxDynamicSharedMemorySize,
                         GEMM_SMEM_BYTES);
    cudaFuncSetAttribute(attn_mma,
                         cudaFuncAttributeMaxDynamicSharedMemorySize,
                         ATT_SMEM_BYTES);

    // all splits in one launch (8 floats/thread)
    split_all<<<9216, 256>>>(x, Wq, Wk, Wv, Wo,
                             xh, xl, wqh, wql, wkh, wkl, wvh, wvl, woh, wol);

    // fused QKV projections -> bf16 hi/lo (128x128 tiles, 2 CTA/SM)
    gemm_qkv<<<dim3(24, MROWS / BM), 256, GEMM_SMEM_BYTES>>>(
        xh, xl, wqh, wql, wkh, wkl, wvh, wvl, bq, bk, bv,
        qh, ql, kh, kl, vh, vl);

    // fused causal GQA attention (Br=64, Bc=32, 2 CTAs/SM, exp2 softmax)
    attn_mma<<<dim3(TSEQ / 64, HQ, BATCH), 128, ATT_SMEM_BYTES>>>(
        qh, ql, kh, kl, vh, vl, ah, al);

    // output projection -> fp32 out
    gemm_out<<<dim3(D_MODEL / BN, MROWS / BM), 256, GEMM_SMEM_BYTES>>>(
        ah, al, woh, wol, bo, out);
}